// round 1
// baseline (speedup 1.0000x reference)
#include <cuda_runtime.h>
#include <math_constants.h>

// RoI max pooling:
//   x:    (1, 256, 64, 64) float32
//   rois: (1, 512, 4) int32  -> (rx, ry, rw, rh)
//   out:  (512, 256, 7, 7) float32
// out[n][c][k][j] = max_{t<dh, s<dw} x[c][ry + dh*k + t][rx + dw*j + s]
// with dh = rh/7, dw = rw/7 (integer div), dh,dw in [1,4].
// Clipping in the reference is provably inactive for these input ranges.

#define C_   256
#define H_   64
#define W_   64
#define N_   512
#define OUTH 7
#define OUTW 7
#define TOTAL (N_ * C_ * OUTH * OUTW)   // 6,422,528

__global__ void __launch_bounds__(256) roipool_kernel(
    const float* __restrict__ x,
    const int*   __restrict__ rois,
    float*       __restrict__ out)
{
    int idx = blockIdx.x * blockDim.x + threadIdx.x;
    if (idx >= TOTAL) return;

    int j = idx % OUTW;
    int k = (idx / OUTW) % OUTH;
    int c = (idx / (OUTH * OUTW)) % C_;
    int n = idx / (OUTH * OUTW * C_);

    // roi: one int4 per thread; 512 distinct values, L1-broadcast.
    const int4 r = __ldg(((const int4*)rois) + n);
    const int rx = r.x, ry = r.y, rw = r.z, rh = r.w;
    const int dh = rh / OUTH;   // warp-uniform (a roi spans 12544 threads)
    const int dw = rw / OUTW;

    const float* base = x + c * (H_ * W_) + (ry + dh * k) * W_ + (rx + dw * j);

    float m = -CUDART_INF_F;
    #pragma unroll 1
    for (int t = 0; t < dh; ++t) {
        const float* rowp = base + t * W_;
        #pragma unroll 1
        for (int s = 0; s < dw; ++s) {
            m = fmaxf(m, __ldg(rowp + s));
        }
    }
    out[idx] = m;
}

extern "C" void kernel_launch(void* const* d_in, const int* in_sizes, int n_in,
                              void* d_out, int out_size)
{
    const float* x    = (const float*)d_in[0];
    const int*   rois = (const int*)  d_in[1];
    float*       out  = (float*)d_out;

    const int threads = 256;
    const int blocks  = (TOTAL + threads - 1) / threads;  // 25088
    roipool_kernel<<<blocks, threads>>>(x, rois, out);
}

// round 2
// speedup vs baseline: 1.3289x; 1.3289x over previous
#include <cuda_runtime.h>
#include <math_constants.h>

// RoI max pooling:
//   x:    (1, 256, 64, 64) float32
//   rois: (1, 512, 4) int32  -> (rx, ry, rw, rh)
//   out:  (512, 256, 7, 7) float32
// out[n][c][k][j] = max_{t<dh, s<dw} x[c][ry + dh*k + t][rx + dw*j + s]
// dh = rh/7, dw = rw/7 (integer div), both in [1,4]. Clipping provably inactive.
//
// Round-2 design: one thread computes the SAME (n,k,j) output for 4 channels
// (c0, c0+64, c0+128, c0+192). All index math amortized 4x; channel offsets are
// compile-time immediates in the LDG; switch(dw) (warp-uniform) unrolls the
// column loop into immediate-offset loads.

#define C_    256
#define H_    64
#define W_    64
#define N_    512
#define CPT   4                      // channels per thread
#define CGRP  (C_ / CPT)             // 64 c0 values
#define CSTR  (CGRP * H_ * W_)       // float stride between handled channels (1 MB)
#define TOTAL2 (N_ * CGRP * 7 * 7)   // 1,605,632 threads (divisible by 256)

__global__ void __launch_bounds__(256) roipool_kernel(
    const float* __restrict__ x,
    const int*   __restrict__ rois,
    float*       __restrict__ out)
{
    int idx = blockIdx.x * blockDim.x + threadIdx.x;

    int kj = idx % 49;
    int j  = kj % 7;
    int k  = kj / 7;
    int c0 = (idx / 49) % CGRP;
    int n  = idx / (49 * CGRP);

    const int4 r = __ldg(((const int4*)rois) + n);
    const int dh = r.w / 7;          // warp-uniform
    const int dw = r.z / 7;          // warp-uniform

    const float* base = x + c0 * (H_ * W_) + (r.y + dh * k) * W_ + (r.x + dw * j);

    float m0 = -CUDART_INF_F, m1 = -CUDART_INF_F;
    float m2 = -CUDART_INF_F, m3 = -CUDART_INF_F;

    // 4 loads with compile-time immediate channel offsets + 4 fmax
    #define ACC(p, off) do {                         \
        m0 = fmaxf(m0, (p)[(off)]);                  \
        m1 = fmaxf(m1, (p)[(off) + CSTR]);           \
        m2 = fmaxf(m2, (p)[(off) + 2 * CSTR]);       \
        m3 = fmaxf(m3, (p)[(off) + 3 * CSTR]);       \
    } while (0)

    switch (dw) {
    case 1:
        #pragma unroll 1
        for (int t = 0; t < dh; ++t) {
            const float* p = base + t * W_;
            ACC(p, 0);
        }
        break;
    case 2:
        #pragma unroll 1
        for (int t = 0; t < dh; ++t) {
            const float* p = base + t * W_;
            ACC(p, 0); ACC(p, 1);
        }
        break;
    case 3:
        #pragma unroll 1
        for (int t = 0; t < dh; ++t) {
            const float* p = base + t * W_;
            ACC(p, 0); ACC(p, 1); ACC(p, 2);
        }
        break;
    default:
        #pragma unroll 1
        for (int t = 0; t < dh; ++t) {
            const float* p = base + t * W_;
            ACC(p, 0); ACC(p, 1); ACC(p, 2); ACC(p, 3);
        }
        break;
    }
    #undef ACC

    // Coalesced stores: for each i, consecutive idx -> consecutive out offsets.
    float* o = out + n * (C_ * 49) + c0 * 49 + kj;
    o[0 * CGRP * 49] = m0;
    o[1 * CGRP * 49] = m1;
    o[2 * CGRP * 49] = m2;
    o[3 * CGRP * 49] = m3;
}

extern "C" void kernel_launch(void* const* d_in, const int* in_sizes, int n_in,
                              void* d_out, int out_size)
{
    const float* x    = (const float*)d_in[0];
    const int*   rois = (const int*)  d_in[1];
    float*       out  = (float*)d_out;

    const int threads = 256;
    const int blocks  = TOTAL2 / threads;   // 6272
    roipool_kernel<<<blocks, threads>>>(x, rois, out);
}